// round 1
// baseline (speedup 1.0000x reference)
#include <cuda_runtime.h>
#include <cuda_bf16.h>

// ---------------- problem constants ----------------
#define BB    2
#define TT    2048
#define DD    1024
#define HH    4
#define KDIM  512            // KD = H*DK
#define VDIM  1024           // VD = H*DV
#define DK    128
#define DV    256
#define CHUNK 64
#define NC    32             // T / CHUNK
#define BT    4096           // B*T
#define LR    16             // LOW_RANK
#define SCALE 0.088388347648318447f   // DK^-0.5
#define EPSN  1e-6f

// ---------------- scratch (no allocations allowed) ----------------
__device__ float g_q  [BT * KDIM];
__device__ float g_k  [BT * KDIM];
__device__ float g_G  [BT * KDIM];   // gk then in-place cumsum
__device__ float g_v  [BT * VDIM];
__device__ float g_g  [BT * VDIM];
__device__ float g_t16[BT * LR];
__device__ float g_o  [BT * VDIM];

// =====================================================================
// Generic fp32 SGEMM: C[M,N] = A[M,K] @ B[K,N], all row-major.
// M,N multiples of 128; K multiple of 8. 256 threads, 8x8 per thread.
// =====================================================================
__global__ void __launch_bounds__(256) sgemm_kernel(
    const float* __restrict__ A, const float* __restrict__ B,
    float* __restrict__ C, int M, int N, int K)
{
    __shared__ float As[8][128];
    __shared__ float Bs[8][128];

    const int tid = threadIdx.x;
    const int ty = tid >> 4;           // 0..15
    const int tx = tid & 15;           // 0..15

    const int mrow = tid >> 1;         // 0..127 (A tile row)
    const int kcol = (tid & 1) * 4;    // 0 or 4
    const int bk   = tid >> 5;         // 0..7   (B tile k-row)
    const int bn   = (tid & 31) * 4;   // 0..124

    const int aRow = blockIdx.y * 128 + mrow;
    const int cCol = blockIdx.x * 128;

    float acc[8][8];
    #pragma unroll
    for (int i = 0; i < 8; i++)
        #pragma unroll
        for (int j = 0; j < 8; j++) acc[i][j] = 0.f;

    for (int k0 = 0; k0 < K; k0 += 8) {
        float4 av = *(const float4*)&A[(long)aRow * K + k0 + kcol];
        float4 bv = *(const float4*)&B[(long)(k0 + bk) * N + cCol + bn];
        __syncthreads();
        As[kcol + 0][mrow] = av.x;
        As[kcol + 1][mrow] = av.y;
        As[kcol + 2][mrow] = av.z;
        As[kcol + 3][mrow] = av.w;
        *(float4*)&Bs[bk][bn] = bv;
        __syncthreads();

        #pragma unroll
        for (int kk = 0; kk < 8; kk++) {
            float4 a0 = *(const float4*)&As[kk][ty * 8];
            float4 a1 = *(const float4*)&As[kk][ty * 8 + 4];
            float4 b0 = *(const float4*)&Bs[kk][tx * 8];
            float4 b1 = *(const float4*)&Bs[kk][tx * 8 + 4];
            float ar[8] = {a0.x,a0.y,a0.z,a0.w,a1.x,a1.y,a1.z,a1.w};
            float br[8] = {b0.x,b0.y,b0.z,b0.w,b1.x,b1.y,b1.z,b1.w};
            #pragma unroll
            for (int i = 0; i < 8; i++)
                #pragma unroll
                for (int j = 0; j < 8; j++)
                    acc[i][j] += ar[i] * br[j];
        }
    }

    const int rowBase = blockIdx.y * 128 + ty * 8;
    const int colBase = cCol + tx * 8;
    #pragma unroll
    for (int i = 0; i < 8; i++) {
        float4 c0 = make_float4(acc[i][0], acc[i][1], acc[i][2], acc[i][3]);
        float4 c1 = make_float4(acc[i][4], acc[i][5], acc[i][6], acc[i][7]);
        *(float4*)&C[(long)(rowBase + i) * N + colBase]     = c0;
        *(float4*)&C[(long)(rowBase + i) * N + colBase + 4] = c1;
    }
}

// =====================================================================
// t16 = x @ Wgk1   (BT x 1024) @ (1024 x 16)
// one block per row, 256 threads
// =====================================================================
__global__ void __launch_bounds__(256) proj16_kernel(
    const float* __restrict__ x, const float* __restrict__ W1)
{
    const int row = blockIdx.x;
    float acc[LR];
    #pragma unroll
    for (int r = 0; r < LR; r++) acc[r] = 0.f;

    for (int kk = threadIdx.x; kk < DD; kk += 256) {
        float xv = x[(long)row * DD + kk];
        const float4* w = (const float4*)&W1[kk * LR];
        float4 w0 = w[0], w1 = w[1], w2 = w[2], w3 = w[3];
        acc[0]  += xv * w0.x;  acc[1]  += xv * w0.y;
        acc[2]  += xv * w0.z;  acc[3]  += xv * w0.w;
        acc[4]  += xv * w1.x;  acc[5]  += xv * w1.y;
        acc[6]  += xv * w1.z;  acc[7]  += xv * w1.w;
        acc[8]  += xv * w2.x;  acc[9]  += xv * w2.y;
        acc[10] += xv * w2.z;  acc[11] += xv * w2.w;
        acc[12] += xv * w3.x;  acc[13] += xv * w3.y;
        acc[14] += xv * w3.z;  acc[15] += xv * w3.w;
    }
    #pragma unroll
    for (int off = 16; off; off >>= 1)
        #pragma unroll
        for (int r = 0; r < LR; r++)
            acc[r] += __shfl_xor_sync(0xffffffffu, acc[r], off);

    __shared__ float red[8][LR];
    int wid = threadIdx.x >> 5, lane = threadIdx.x & 31;
    if (lane == 0)
        #pragma unroll
        for (int r = 0; r < LR; r++) red[wid][r] = acc[r];
    __syncthreads();
    if (threadIdx.x < LR) {
        float s = 0.f;
        #pragma unroll
        for (int w = 0; w < 8; w++) s += red[w][threadIdx.x];
        g_t16[row * LR + threadIdx.x] = s;
    }
}

// =====================================================================
// gk = log_sigmoid(t16 @ Wgk2 + b) / 16      one block per row, 512 thr
// =====================================================================
__global__ void __launch_bounds__(512) gk_kernel(
    const float* __restrict__ W2, const float* __restrict__ bias)
{
    const int row = blockIdx.x;
    __shared__ float ts[LR];
    if (threadIdx.x < LR) ts[threadIdx.x] = g_t16[row * LR + threadIdx.x];
    __syncthreads();
    const int kd = threadIdx.x;
    float s = bias[kd];
    #pragma unroll
    for (int r = 0; r < LR; r++) s += ts[r] * W2[r * KDIM + kd];
    // stable log_sigmoid
    float ls = fminf(s, 0.f) - log1pf(expf(-fabsf(s)));
    g_G[(long)row * KDIM + kd] = ls * (1.f / 16.f);
}

// =====================================================================
// per-chunk cumsum of gk (in place). grid = B*NC, block = 512 (kd cols)
// =====================================================================
__global__ void __launch_bounds__(512) cumsum_kernel()
{
    const int blk = blockIdx.x;
    const int b = blk >> 5, n = blk & 31;
    const long base = ((long)(b * TT + n * CHUNK)) * KDIM + threadIdx.x;
    float run = 0.f;
    for (int c = 0; c < CHUNK; c++) {
        run += g_G[base + (long)c * KDIM];
        g_G[base + (long)c * KDIM] = run;
    }
}

// =====================================================================
// Sequential inter-chunk scan + o_inter.
// grid = B*H*8 (8 v-slices of 32), block = 256. S (128x32) in smem.
// =====================================================================
#define SCAN_SMEM_BYTES (23296 * 4)
__global__ void __launch_bounds__(256) scan_kernel()
{
    extern __shared__ float sm[];
    float* S   = sm;            // 128*32
    float* qg  = sm + 4096;     // 64*128
    float* kbT = sm + 12288;    // 128*68 (padded rows)
    float* v_s = sm + 20992;    // 64*32
    float* eGl = sm + 23040;    // 128
    float* Gls = sm + 23168;    // 128

    const int blk = blockIdx.x;
    const int vs = blk & 7, h = (blk >> 3) & 3, b = blk >> 5;
    const int tid = threadIdx.x;
    const int colK = h * DK;
    const int colV = h * DV + vs * 32;

    for (int i = tid; i < 4096; i += 256) S[i] = 0.f;

    for (int n = 0; n < NC; n++) {
        const int t0 = b * TT + n * CHUNK;
        if (tid < 128) {
            float gl = g_G[(long)(t0 + 63) * KDIM + colK + tid];
            Gls[tid] = gl;
            eGl[tid] = expf(gl);
        }
        __syncthreads();
        // stage qg, k_bar^T
        #pragma unroll 4
        for (int it = 0; it < 32; it++) {
            int idx = tid + 256 * it;           // 0..8191
            int c = idx >> 7, dk = idx & 127;
            long gidx = (long)(t0 + c) * KDIM + colK + dk;
            float Gv = g_G[gidx];
            qg[idx] = g_q[gidx] * expf(Gv) * SCALE;
            kbT[dk * 68 + c] = g_k[gidx] * expf(Gls[dk] - Gv);
        }
        #pragma unroll
        for (int it = 0; it < 8; it++) {
            int idx = tid + 256 * it;           // 0..2047
            int c = idx >> 5, vi = idx & 31;
            v_s[idx] = g_v[(long)(t0 + c) * VDIM + colV + vi];
        }
        __syncthreads();

        // o_inter[c, vi] = sum_k qg[c,k] * S[k,vi]
        {
            const int vi = tid & 31, c0 = tid >> 5;
            float acc[8] = {0,0,0,0,0,0,0,0};
            for (int k4 = 0; k4 < 128; k4 += 4) {
                float s0 = S[(k4 + 0) * 32 + vi];
                float s1 = S[(k4 + 1) * 32 + vi];
                float s2 = S[(k4 + 2) * 32 + vi];
                float s3 = S[(k4 + 3) * 32 + vi];
                #pragma unroll
                for (int j = 0; j < 8; j++) {
                    float4 qv = *(const float4*)&qg[(c0 + 8 * j) * 128 + k4];
                    acc[j] += qv.x * s0 + qv.y * s1 + qv.z * s2 + qv.w * s3;
                }
            }
            #pragma unroll
            for (int j = 0; j < 8; j++)
                g_o[(long)(t0 + c0 + 8 * j) * VDIM + colV + vi] = acc[j];
        }
        __syncthreads();

        // S[k,vi] = eGl[k]*S[k,vi] + sum_c kbT[k,c] * v_s[c,vi]
        {
            const int vi = tid & 31, k0 = tid >> 5;
            float upd[16];
            #pragma unroll
            for (int i = 0; i < 16; i++)
                upd[i] = eGl[k0 + 8 * i] * S[(k0 + 8 * i) * 32 + vi];
            for (int c4 = 0; c4 < 64; c4 += 4) {
                float v0 = v_s[(c4 + 0) * 32 + vi];
                float v1 = v_s[(c4 + 1) * 32 + vi];
                float v2 = v_s[(c4 + 2) * 32 + vi];
                float v3 = v_s[(c4 + 3) * 32 + vi];
                #pragma unroll
                for (int i = 0; i < 16; i++) {
                    float4 kv = *(const float4*)&kbT[(k0 + 8 * i) * 68 + c4];
                    upd[i] += kv.x * v0 + kv.y * v1 + kv.z * v2 + kv.w * v3;
                }
            }
            #pragma unroll
            for (int i = 0; i < 16; i++)
                S[(k0 + 8 * i) * 32 + vi] = upd[i];
        }
        __syncthreads();
    }
}

// =====================================================================
// Intra-chunk attention: A = tril(qg @ kg^T), o += A @ v
// grid = B*H*NC = 256, block = 256.
// =====================================================================
#define INTRA_SMEM_BYTES (25600 * 4)
__global__ void __launch_bounds__(256) intra_kernel()
{
    extern __shared__ float sm[];
    float* qg  = sm;            // 64*128
    float* kgT = sm + 8192;     // 128*68
    float* A   = sm + 16896;    // 64*68
    float* v_s = sm + 21248;    // 64*68

    const int blk = blockIdx.x;
    const int n = blk & 31, h = (blk >> 5) & 3, b = blk >> 7;
    const int tid = threadIdx.x;
    const int t0 = b * TT + n * CHUNK;
    const int colK = h * DK;
    const int colV = h * DV;

    // stage qg and kg^T
    #pragma unroll 4
    for (int it = 0; it < 32; it++) {
        int idx = tid + 256 * it;
        int c = idx >> 7, dk = idx & 127;
        long gidx = (long)(t0 + c) * KDIM + colK + dk;
        float Gv = g_G[gidx];
        qg[c * 128 + dk] = g_q[gidx] * expf(Gv) * SCALE;
        kgT[dk * 68 + c] = g_k[gidx] * expf(-Gv);
    }
    __syncthreads();

    // A[i,j] = tril( sum_k qg[i,k]*kg[j,k] )
    {
        const int jg = tid & 15, ig = tid >> 4;
        const int i0 = ig * 4, j0 = jg * 4;
        float acc[4][4];
        #pragma unroll
        for (int ii = 0; ii < 4; ii++)
            #pragma unroll
            for (int jj = 0; jj < 4; jj++) acc[ii][jj] = 0.f;
        for (int k4 = 0; k4 < 128; k4 += 4) {
            float4 a[4], bt[4];
            #pragma unroll
            for (int ii = 0; ii < 4; ii++)
                a[ii] = *(const float4*)&qg[(i0 + ii) * 128 + k4];
            #pragma unroll
            for (int kk = 0; kk < 4; kk++)
                bt[kk] = *(const float4*)&kgT[(k4 + kk) * 68 + j0];
            #pragma unroll
            for (int ii = 0; ii < 4; ii++) {
                float4 av = a[ii];
                acc[ii][0] += av.x*bt[0].x + av.y*bt[1].x + av.z*bt[2].x + av.w*bt[3].x;
                acc[ii][1] += av.x*bt[0].y + av.y*bt[1].y + av.z*bt[2].y + av.w*bt[3].y;
                acc[ii][2] += av.x*bt[0].z + av.y*bt[1].z + av.z*bt[2].z + av.w*bt[3].z;
                acc[ii][3] += av.x*bt[0].w + av.y*bt[1].w + av.z*bt[2].w + av.w*bt[3].w;
            }
        }
        #pragma unroll
        for (int ii = 0; ii < 4; ii++)
            #pragma unroll
            for (int jj = 0; jj < 4; jj++)
                A[(i0 + ii) * 68 + j0 + jj] =
                    (j0 + jj <= i0 + ii) ? acc[ii][jj] : 0.f;
    }
    __syncthreads();

    // o += A @ v (vd in 4 tiles of 64)
    const int ug = tid & 15, cg = tid >> 4;
    const int c0 = cg * 4, u0 = ug * 4;
    for (int vt = 0; vt < 4; vt++) {
        #pragma unroll
        for (int it = 0; it < 16; it++) {
            int idx = tid + 256 * it;          // 0..4095
            int c = idx >> 6, u = idx & 63;
            v_s[c * 68 + u] = g_v[(long)(t0 + c) * VDIM + colV + vt * 64 + u];
        }
        __syncthreads();
        float acc[4][4];
        #pragma unroll
        for (int ii = 0; ii < 4; ii++)
            #pragma unroll
            for (int jj = 0; jj < 4; jj++) acc[ii][jj] = 0.f;
        for (int j4 = 0; j4 < 64; j4 += 4) {
            float4 a[4], vv[4];
            #pragma unroll
            for (int ii = 0; ii < 4; ii++)
                a[ii] = *(const float4*)&A[(c0 + ii) * 68 + j4];
            #pragma unroll
            for (int jj = 0; jj < 4; jj++)
                vv[jj] = *(const float4*)&v_s[(j4 + jj) * 68 + u0];
            #pragma unroll
            for (int ii = 0; ii < 4; ii++) {
                float4 av = a[ii];
                acc[ii][0] += av.x*vv[0].x + av.y*vv[1].x + av.z*vv[2].x + av.w*vv[3].x;
                acc[ii][1] += av.x*vv[0].y + av.y*vv[1].y + av.z*vv[2].y + av.w*vv[3].y;
                acc[ii][2] += av.x*vv[0].z + av.y*vv[1].z + av.z*vv[2].z + av.w*vv[3].z;
                acc[ii][3] += av.x*vv[0].w + av.y*vv[1].w + av.z*vv[2].w + av.w*vv[3].w;
            }
        }
        #pragma unroll
        for (int ii = 0; ii < 4; ii++) {
            float4* op = (float4*)&g_o[(long)(t0 + c0 + ii) * VDIM + colV + vt * 64 + u0];
            float4 cur = *op;
            cur.x += acc[ii][0]; cur.y += acc[ii][1];
            cur.z += acc[ii][2]; cur.w += acc[ii][3];
            *op = cur;
        }
        __syncthreads();
    }
}

// =====================================================================
// Per-head RMS norm + SiLU gate. grid = BT*H, block = 256 (= DV)
// =====================================================================
__global__ void __launch_bounds__(256) norm_gate_kernel(const float* __restrict__ gnw)
{
    const int blk = blockIdx.x;
    const int row = blk >> 2, h = blk & 3;
    const long idx = (long)row * VDIM + h * DV + threadIdx.x;
    float xv = g_o[idx];
    float ss = xv * xv;
    #pragma unroll
    for (int off = 16; off; off >>= 1)
        ss += __shfl_xor_sync(0xffffffffu, ss, off);
    __shared__ float red[8];
    __shared__ float stot;
    int wid = threadIdx.x >> 5, lane = threadIdx.x & 31;
    if (lane == 0) red[wid] = ss;
    __syncthreads();
    if (threadIdx.x == 0) {
        float s = 0.f;
        #pragma unroll
        for (int w = 0; w < 8; w++) s += red[w];
        stot = s;
    }
    __syncthreads();
    float mean = stot * (1.f / 256.f);
    float r = rsqrtf(mean + EPSN);
    float gv = g_g[idx];
    float sig = 1.f / (1.f + expf(-gv));
    g_o[idx] = xv * r * gnw[threadIdx.x] * (gv * sig);
}

// =====================================================================
// launch
// =====================================================================
extern "C" void kernel_launch(void* const* d_in, const int* in_sizes, int n_in,
                              void* d_out, int out_size)
{
    const float* x    = (const float*)d_in[0];
    const float* Wq   = (const float*)d_in[1];
    const float* Wk   = (const float*)d_in[2];
    const float* Wv   = (const float*)d_in[3];
    const float* Wg   = (const float*)d_in[4];
    const float* Wgk1 = (const float*)d_in[5];
    const float* Wgk2 = (const float*)d_in[6];
    const float* bgk2 = (const float*)d_in[7];
    const float* gnw  = (const float*)d_in[8];
    const float* Wo   = (const float*)d_in[9];
    float* out = (float*)d_out;

    float *q, *k, *G, *v, *g, *o;
    cudaGetSymbolAddress((void**)&q, g_q);
    cudaGetSymbolAddress((void**)&k, g_k);
    cudaGetSymbolAddress((void**)&G, g_G);
    cudaGetSymbolAddress((void**)&v, g_v);
    cudaGetSymbolAddress((void**)&g, g_g);
    cudaGetSymbolAddress((void**)&o, g_o);

    cudaFuncSetAttribute(scan_kernel,  cudaFuncAttributeMaxDynamicSharedMemorySize, SCAN_SMEM_BYTES);
    cudaFuncSetAttribute(intra_kernel, cudaFuncAttributeMaxDynamicSharedMemorySize, INTRA_SMEM_BYTES);

    // projections
    sgemm_kernel<<<dim3(KDIM / 128, BT / 128), 256>>>(x, Wq, q, BT, KDIM, DD);
    sgemm_kernel<<<dim3(KDIM / 128, BT / 128), 256>>>(x, Wk, k, BT, KDIM, DD);
    sgemm_kernel<<<dim3(VDIM / 128, BT / 128), 256>>>(x, Wv, v, BT, VDIM, DD);
    sgemm_kernel<<<dim3(VDIM / 128, BT / 128), 256>>>(x, Wg, g, BT, VDIM, DD);

    // gate path
    proj16_kernel<<<BT, 256>>>(x, Wgk1);
    gk_kernel<<<BT, 512>>>(Wgk2, bgk2);
    cumsum_kernel<<<BB * NC, 512>>>();

    // attention
    scan_kernel<<<BB * HH * 8, 256, SCAN_SMEM_BYTES>>>();
    intra_kernel<<<NC * BB * HH, 256, INTRA_SMEM_BYTES>>>();

    // norm/gate + output projection
    norm_gate_kernel<<<BT * HH, 256>>>(gnw);
    sgemm_kernel<<<dim3(DD / 128, BT / 128), 256>>>(o, Wo, out, BT, DD, VDIM);
}

// round 4
// speedup vs baseline: 2.0489x; 2.0489x over previous
#include <cuda_runtime.h>
#include <cuda_bf16.h>
#include <cstdint>

// ---------------- problem constants ----------------
#define BB    2
#define TT    2048
#define DD    1024
#define HH    4
#define KDIM  512            // KD = H*DK
#define VDIM  1024           // VD = H*DV
#define DK    128
#define DV    256
#define CHUNK 64
#define NC    32             // T / CHUNK
#define BT    4096           // B*T
#define LR    16             // LOW_RANK
#define SCALE 0.088388347648318447f   // DK^-0.5
#define EPSN  1e-6f

// ---------------- scratch (no allocations allowed) ----------------
__device__ float g_q  [BT * KDIM];
__device__ float g_k  [BT * KDIM];
__device__ float g_G  [BT * KDIM];   // gk then in-place cumsum
__device__ float g_v  [BT * VDIM];
__device__ float g_g  [BT * VDIM];
__device__ float g_t16[BT * LR];
__device__ float g_o  [BT * VDIM];
__device__ float g_xr [BT * DD];          // x rounded to tf32
__device__ float g_WT [3072 * DD];        // [Wq;Wk;Wv;Wg]^T rows, K-major, tf32-rounded
__device__ float g_WoT[DD * VDIM];        // Wo^T, K-major, tf32-rounded

// =====================================================================
// PTX helpers (baseline compute_103-safe: mma.sync / ldmatrix / cp.async)
// =====================================================================
__device__ __forceinline__ uint32_t smem_u32(const void* p) {
    uint32_t a;
    asm("{ .reg .u64 t; cvta.to.shared.u64 t, %1; cvt.u32.u64 %0, t; }" : "=r"(a) : "l"(p));
    return a;
}
__device__ __forceinline__ float tf32_rna(float x) {
    float r; asm("cvt.rna.tf32.f32 %0, %1;" : "=f"(r) : "f"(x)); return r;
}
__device__ __forceinline__ void cp16(uint32_t saddr, const void* gaddr) {
    asm volatile("cp.async.ca.shared.global [%0], [%1], 16;" :: "r"(saddr), "l"(gaddr));
}
__device__ __forceinline__ void cp_commit() {
    asm volatile("cp.async.commit_group;" ::: "memory");
}
template <int N>
__device__ __forceinline__ void cp_wait() {
    asm volatile("cp.async.wait_group %0;" :: "n"(N) : "memory");
}
__device__ __forceinline__ void ldm_x4(uint32_t& r0, uint32_t& r1, uint32_t& r2,
                                       uint32_t& r3, uint32_t addr) {
    asm volatile("ldmatrix.sync.aligned.m8n8.x4.shared.b16 {%0,%1,%2,%3}, [%4];"
                 : "=r"(r0), "=r"(r1), "=r"(r2), "=r"(r3) : "r"(addr));
}
__device__ __forceinline__ void mma_tf32(float* c, const uint32_t* a, const uint32_t* b) {
    asm volatile(
        "mma.sync.aligned.m16n8k8.row.col.f32.tf32.tf32.f32 "
        "{%0,%1,%2,%3}, {%4,%5,%6,%7}, {%8,%9}, {%0,%1,%2,%3};"
        : "+f"(c[0]), "+f"(c[1]), "+f"(c[2]), "+f"(c[3])
        : "r"(a[0]), "r"(a[1]), "r"(a[2]), "r"(a[3]), "r"(b[0]), "r"(b[1]));
}

// =====================================================================
// tf32 mma.sync GEMM: C tile 128x128, K=1024, BK=32, double-buffered
// cp.async. A: [M,1024] K-major, Bmat: [Ntot,1024] K-major (both
// tf32-prerounded). mode 0: scatter N-blocks to q/k/v/g. mode 1: dq.
// =====================================================================
#define AST 36                               // smem row stride (floats)
#define STAGE_F (128 * AST)                  // 4608 floats per matrix
#define GEMM_SMEM (4 * STAGE_F * 4)          // 2 stages x (A,B) = 73728 B

__global__ void __launch_bounds__(256)
gemm_mma_kernel(const float* __restrict__ Amat, const float* __restrict__ Bmat,
                float* __restrict__ dq, float* __restrict__ dkk,
                float* __restrict__ dvv, float* __restrict__ dgg, int mode)
{
    extern __shared__ float sm[];
    // layout: A0 | B0 | A1 | B1
    const uint32_t sb = smem_u32(sm);
    const int tid = threadIdx.x;
    const int wid = tid >> 5, lane = tid & 31;
    const int m0 = blockIdx.y * 128;
    const int n0 = blockIdx.x * 128;

    const int warpM0 = (wid >> 2) * 64;      // 0 or 64
    const int warpN0 = (wid & 3) * 32;       // 0,32,64,96

    // per-lane ldmatrix address components
    const int aRow = warpM0 + (lane & 15);
    const int aCol = (lane >> 4) << 2;                       // 0 or 4
    const int bRow = warpN0 + (lane & 7) + ((lane >> 4) << 3);
    const int bCol = ((lane >> 3) & 1) << 2;                 // 0 or 4

    // cp.async mapping: chunk c = tid + 256*i; row = c>>3; j = c&7
    float c[4][4][4];
    #pragma unroll
    for (int mt = 0; mt < 4; mt++)
        #pragma unroll
        for (int nt = 0; nt < 4; nt++)
            #pragma unroll
            for (int e = 0; e < 4; e++) c[mt][nt][e] = 0.f;

    auto issue = [&](int kt, int s) {
        const uint32_t sA = sb + s * 2 * STAGE_F * 4;
        const uint32_t sB = sA + STAGE_F * 4;
        #pragma unroll
        for (int i = 0; i < 4; i++) {
            const int ck = tid + 256 * i;
            const int row = ck >> 3, j = ck & 7;
            const int gc = kt * 32 + j * 4;
            cp16(sA + 4 * (row * AST + j * 4), &Amat[(long)(m0 + row) * DD + gc]);
            cp16(sB + 4 * (row * AST + j * 4), &Bmat[(long)(n0 + row) * DD + gc]);
        }
        cp_commit();
    };

    issue(0, 0);

    for (int it = 0; it < 32; it++) {
        if (it + 1 < 32) { issue(it + 1, (it + 1) & 1); cp_wait<1>(); }
        else             { cp_wait<0>(); }
        __syncthreads();

        const uint32_t sA = sb + (it & 1) * 2 * STAGE_F * 4;
        const uint32_t sB = sA + STAGE_F * 4;

        #pragma unroll
        for (int ks = 0; ks < 4; ks++) {
            const int k0 = ks * 8;
            uint32_t a[4][4], b[4][2];
            #pragma unroll
            for (int mt = 0; mt < 4; mt++)
                ldm_x4(a[mt][0], a[mt][1], a[mt][2], a[mt][3],
                       sA + 4 * ((aRow + mt * 16) * AST + k0 + aCol));
            #pragma unroll
            for (int np = 0; np < 2; np++) {
                uint32_t r0, r1, r2, r3;
                ldm_x4(r0, r1, r2, r3,
                       sB + 4 * ((bRow + np * 16) * AST + k0 + bCol));
                b[2 * np][0] = r0; b[2 * np][1] = r1;
                b[2 * np + 1][0] = r2; b[2 * np + 1][1] = r3;
            }
            #pragma unroll
            for (int mt = 0; mt < 4; mt++)
                #pragma unroll
                for (int nt = 0; nt < 4; nt++)
                    mma_tf32(c[mt][nt], a[mt], b[nt]);
        }
        __syncthreads();
    }

    // epilogue
    float* dst; int ldc, colBase;
    if (mode == 1) { dst = dq; ldc = 1024; colBase = n0; }
    else {
        const int nb = blockIdx.x;
        if (nb < 4)       { dst = dq;  ldc = 512;  colBase = nb * 128; }
        else if (nb < 8)  { dst = dkk; ldc = 512;  colBase = (nb - 4) * 128; }
        else if (nb < 16) { dst = dvv; ldc = 1024; colBase = (nb - 8) * 128; }
        else              { dst = dgg; ldc = 1024; colBase = (nb - 16) * 128; }
    }
    const int rB = m0 + warpM0 + (lane >> 2);
    const int cB = colBase + warpN0 + 2 * (lane & 3);
    #pragma unroll
    for (int mt = 0; mt < 4; mt++)
        #pragma unroll
        for (int nt = 0; nt < 4; nt++) {
            const long r0 = (long)(rB + mt * 16) * ldc + cB + nt * 8;
            const long r1 = (long)(rB + mt * 16 + 8) * ldc + cB + nt * 8;
            *(float2*)&dst[r0] = make_float2(c[mt][nt][0], c[mt][nt][1]);
            *(float2*)&dst[r1] = make_float2(c[mt][nt][2], c[mt][nt][3]);
        }
}

// =====================================================================
// weight transpose + tf32 round:  WT[n*1024 + k] = rna(W[k*N + n])
// =====================================================================
__global__ void __launch_bounds__(256) transpose_rna_kernel(
    const float* __restrict__ W, float* __restrict__ WT, int N)
{
    __shared__ float t[32][33];
    const int tx = threadIdx.x & 31, ty = threadIdx.x >> 5;   // 32x8
    const int n0 = blockIdx.x * 32, k0 = blockIdx.y * 32;
    #pragma unroll
    for (int i = 0; i < 4; i++)
        t[ty + 8 * i][tx] = W[(long)(k0 + ty + 8 * i) * N + n0 + tx];
    __syncthreads();
    #pragma unroll
    for (int i = 0; i < 4; i++)
        WT[(long)(n0 + ty + 8 * i) * DD + k0 + tx] = tf32_rna(t[tx][ty + 8 * i]);
}

// x -> tf32-rounded copy
__global__ void __launch_bounds__(256) round_x_kernel(const float* __restrict__ x)
{
    const int i = (blockIdx.x * 256 + threadIdx.x) * 4;
    float4 v = *(const float4*)&x[i];
    v.x = tf32_rna(v.x); v.y = tf32_rna(v.y);
    v.z = tf32_rna(v.z); v.w = tf32_rna(v.w);
    *(float4*)&g_xr[i] = v;
}

// =====================================================================
// t16 = x @ Wgk1   (BT x 1024) @ (1024 x 16); one block per row
// =====================================================================
__global__ void __launch_bounds__(256) proj16_kernel(
    const float* __restrict__ x, const float* __restrict__ W1)
{
    const int row = blockIdx.x;
    float acc[LR];
    #pragma unroll
    for (int r = 0; r < LR; r++) acc[r] = 0.f;

    for (int kk = threadIdx.x; kk < DD; kk += 256) {
        float xv = x[(long)row * DD + kk];
        const float4* w = (const float4*)&W1[kk * LR];
        float4 w0 = w[0], w1 = w[1], w2 = w[2], w3 = w[3];
        acc[0]  += xv * w0.x;  acc[1]  += xv * w0.y;
        acc[2]  += xv * w0.z;  acc[3]  += xv * w0.w;
        acc[4]  += xv * w1.x;  acc[5]  += xv * w1.y;
        acc[6]  += xv * w1.z;  acc[7]  += xv * w1.w;
        acc[8]  += xv * w2.x;  acc[9]  += xv * w2.y;
        acc[10] += xv * w2.z;  acc[11] += xv * w2.w;
        acc[12] += xv * w3.x;  acc[13] += xv * w3.y;
        acc[14] += xv * w3.z;  acc[15] += xv * w3.w;
    }
    #pragma unroll
    for (int off = 16; off; off >>= 1)
        #pragma unroll
        for (int r = 0; r < LR; r++)
            acc[r] += __shfl_xor_sync(0xffffffffu, acc[r], off);

    __shared__ float red[8][LR];
    int wid = threadIdx.x >> 5, lane = threadIdx.x & 31;
    if (lane == 0)
        #pragma unroll
        for (int r = 0; r < LR; r++) red[wid][r] = acc[r];
    __syncthreads();
    if (threadIdx.x < LR) {
        float s = 0.f;
        #pragma unroll
        for (int w = 0; w < 8; w++) s += red[w][threadIdx.x];
        g_t16[row * LR + threadIdx.x] = s;
    }
}

// =====================================================================
// gk = log_sigmoid(t16 @ Wgk2 + b) / 16
// =====================================================================
__global__ void __launch_bounds__(512) gk_kernel(
    const float* __restrict__ W2, const float* __restrict__ bias)
{
    const int row = blockIdx.x;
    __shared__ float ts[LR];
    if (threadIdx.x < LR) ts[threadIdx.x] = g_t16[row * LR + threadIdx.x];
    __syncthreads();
    const int kd = threadIdx.x;
    float s = bias[kd];
    #pragma unroll
    for (int r = 0; r < LR; r++) s += ts[r] * W2[r * KDIM + kd];
    float ls = fminf(s, 0.f) - log1pf(expf(-fabsf(s)));
    g_G[(long)row * KDIM + kd] = ls * (1.f / 16.f);
}

// per-chunk cumsum of gk (in place)
__global__ void __launch_bounds__(512) cumsum_kernel()
{
    const int blk = blockIdx.x;
    const int b = blk >> 5, n = blk & 31;
    const long base = ((long)(b * TT + n * CHUNK)) * KDIM + threadIdx.x;
    float run = 0.f;
    for (int c = 0; c < CHUNK; c++) {
        run += g_G[base + (long)c * KDIM];
        g_G[base + (long)c * KDIM] = run;
    }
}

// =====================================================================
// Sequential inter-chunk scan + o_inter.
// =====================================================================
#define SCAN_SMEM_BYTES (23296 * 4)
__global__ void __launch_bounds__(256) scan_kernel()
{
    extern __shared__ float sm[];
    float* S   = sm;            // 128*32
    float* qg  = sm + 4096;     // 64*128
    float* kbT = sm + 12288;    // 128*68 (padded rows)
    float* v_s = sm + 20992;    // 64*32
    float* eGl = sm + 23040;    // 128
    float* Gls = sm + 23168;    // 128

    const int blk = blockIdx.x;
    const int vs = blk & 7, h = (blk >> 3) & 3, b = blk >> 5;
    const int tid = threadIdx.x;
    const int colK = h * DK;
    const int colV = h * DV + vs * 32;

    for (int i = tid; i < 4096; i += 256) S[i] = 0.f;

    for (int n = 0; n < NC; n++) {
        const int t0 = b * TT + n * CHUNK;
        if (tid < 128) {
            float gl = g_G[(long)(t0 + 63) * KDIM + colK + tid];
            Gls[tid] = gl;
            eGl[tid] = expf(gl);
        }
        __syncthreads();
        #pragma unroll 4
        for (int it = 0; it < 32; it++) {
            int idx = tid + 256 * it;           // 0..8191
            int c = idx >> 7, dk = idx & 127;
            long gidx = (long)(t0 + c) * KDIM + colK + dk;
            float Gv = g_G[gidx];
            qg[idx] = g_q[gidx] * expf(Gv) * SCALE;
            kbT[dk * 68 + c] = g_k[gidx] * expf(Gls[dk] - Gv);
        }
        #pragma unroll
        for (int it = 0; it < 8; it++) {
            int idx = tid + 256 * it;           // 0..2047
            int c = idx >> 5, vi = idx & 31;
            v_s[idx] = g_v[(long)(t0 + c) * VDIM + colV + vi];
        }
        __syncthreads();

        {
            const int vi = tid & 31, c0 = tid >> 5;
            float acc[8] = {0,0,0,0,0,0,0,0};
            for (int k4 = 0; k4 < 128; k4 += 4) {
                float s0 = S[(k4 + 0) * 32 + vi];
                float s1 = S[(k4 + 1) * 32 + vi];
                float s2 = S[(k4 + 2) * 32 + vi];
                float s3 = S[(k4 + 3) * 32 + vi];
                #pragma unroll
                for (int j = 0; j < 8; j++) {
                    float4 qv = *(const float4*)&qg[(c0 + 8 * j) * 128 + k4];
                    acc[j] += qv.x * s0 + qv.y * s1 + qv.z * s2 + qv.w * s3;
                }
            }
            #pragma unroll
            for (int j = 0; j < 8; j++)
                g_o[(long)(t0 + c0 + 8 * j) * VDIM + colV + vi] = acc[j];
        }
        __syncthreads();

        {
            const int vi = tid & 31, k0 = tid >> 5;
            float upd[16];
            #pragma unroll
            for (int i = 0; i < 16; i++)
                upd[i] = eGl[k0 + 8 * i] * S[(k0 + 8 * i) * 32 + vi];
            for (int c4 = 0; c4 < 64; c4 += 4) {
                float v0 = v_s[(c4 + 0) * 32 + vi];
                float v1 = v_s[(c4 + 1) * 32 + vi];
                float v2 = v_s[(c4 + 2) * 32 + vi];
                float v3 = v_s[(c4 + 3) * 32 + vi];
                #pragma unroll
                for (int i = 0; i < 16; i++) {
                    float4 kv = *(const float4*)&kbT[(k0 + 8 * i) * 68 + c4];
                    upd[i] += kv.x * v0 + kv.y * v1 + kv.z * v2 + kv.w * v3;
                }
            }
            #pragma unroll
            for (int i = 0; i < 16; i++)
                S[(k0 + 8 * i) * 32 + vi] = upd[i];
        }
        __syncthreads();
    }
}

// =====================================================================
// Intra-chunk attention: A = tril(qg @ kg^T), o += A @ v
// =====================================================================
#define INTRA_SMEM_BYTES (25600 * 4)
__global__ void __launch_bounds__(256) intra_kernel()
{
    extern __shared__ float sm[];
    float* qg  = sm;            // 64*128
    float* kgT = sm + 8192;     // 128*68
    float* A   = sm + 16896;    // 64*68
    float* v_s = sm + 21248;    // 64*68

    const int blk = blockIdx.x;
    const int n = blk & 31, h = (blk >> 5) & 3, b = blk >> 7;
    const int tid = threadIdx.x;
    const int t0 = b * TT + n * CHUNK;
    const int colK = h * DK;
    const int colV = h * DV;

    #pragma unroll 4
    for (int it = 0; it < 32; it++) {
        int idx = tid + 256 * it;
        int c = idx >> 7, dk = idx & 127;
        long gidx = (long)(t0 + c) * KDIM + colK + dk;
        float Gv = g_G[gidx];
        qg[c * 128 + dk] = g_q[gidx] * expf(Gv) * SCALE;
        kgT[dk * 68 + c] = g_k[gidx] * expf(-Gv);
    }
    __syncthreads();

    {
        const int jg = tid & 15, ig = tid >> 4;
        const int i0 = ig * 4, j0 = jg * 4;
        float acc[4][4];
        #pragma unroll
        for (int ii = 0; ii < 4; ii++)
            #pragma unroll
            for (int jj = 0; jj < 4; jj++) acc[ii][jj] = 0.f;
        for (int k4 = 0; k4 < 128; k4 += 4) {
            float4 a[4], bt[4];
            #pragma unroll
            for (int ii = 0; ii < 4; ii++)
                a[ii] = *(const float4*)&qg[(i0 + ii) * 128 + k4];
            #pragma unroll
            for (int kk = 0; kk < 4; kk++)
                bt[kk] = *(const float4*)&kgT[(k4 + kk) * 68 + j0];
            #pragma unroll
            for (int ii = 0; ii < 4; ii++) {
                float4 av = a[ii];
                acc[ii][0] += av.x*bt[0].x + av.y*bt[1].x + av.z*bt[2].x + av.w*bt[3].x;
                acc[ii][1] += av.x*bt[0].y + av.y*bt[1].y + av.z*bt[2].y + av.w*bt[3].y;
                acc[ii][2] += av.x*bt[0].z + av.y*bt[1].z + av.z*bt[2].z + av.w*bt[3].z;
                acc[ii][3] += av.x*bt[0].w + av.y*bt[1].w + av.z*bt[2].w + av.w*bt[3].w;
            }
        }
        #pragma unroll
        for (int ii = 0; ii < 4; ii++)
            #pragma unroll
            for (int jj = 0; jj < 4; jj++)
                A[(i0 + ii) * 68 + j0 + jj] =
                    (j0 + jj <= i0 + ii) ? acc[ii][jj] : 0.f;
    }
    __syncthreads();

    const int ug = tid & 15, cg = tid >> 4;
    const int c0 = cg * 4, u0 = ug * 4;
    for (int vt = 0; vt < 4; vt++) {
        #pragma unroll
        for (int it = 0; it < 16; it++) {
            int idx = tid + 256 * it;          // 0..4095
            int c = idx >> 6, u = idx & 63;
            v_s[c * 68 + u] = g_v[(long)(t0 + c) * VDIM + colV + vt * 64 + u];
        }
        __syncthreads();
        float acc[4][4];
        #pragma unroll
        for (int ii = 0; ii < 4; ii++)
            #pragma unroll
            for (int jj = 0; jj < 4; jj++) acc[ii][jj] = 0.f;
        for (int j4 = 0; j4 < 64; j4 += 4) {
            float4 a[4], vv[4];
            #pragma unroll
            for (int ii = 0; ii < 4; ii++)
                a[ii] = *(const float4*)&A[(c0 + ii) * 68 + j4];
            #pragma unroll
            for (int jj = 0; jj < 4; jj++)
                vv[jj] = *(const float4*)&v_s[(j4 + jj) * 68 + u0];
            #pragma unroll
            for (int ii = 0; ii < 4; ii++) {
                float4 av = a[ii];
                acc[ii][0] += av.x*vv[0].x + av.y*vv[1].x + av.z*vv[2].x + av.w*vv[3].x;
                acc[ii][1] += av.x*vv[0].y + av.y*vv[1].y + av.z*vv[2].y + av.w*vv[3].y;
                acc[ii][2] += av.x*vv[0].z + av.y*vv[1].z + av.z*vv[2].z + av.w*vv[3].z;
                acc[ii][3] += av.x*vv[0].w + av.y*vv[1].w + av.z*vv[2].w + av.w*vv[3].w;
            }
        }
        #pragma unroll
        for (int ii = 0; ii < 4; ii++) {
            float4* op = (float4*)&g_o[(long)(t0 + c0 + ii) * VDIM + colV + vt * 64 + u0];
            float4 cur = *op;
            cur.x += acc[ii][0]; cur.y += acc[ii][1];
            cur.z += acc[ii][2]; cur.w += acc[ii][3];
            *op = cur;
        }
        __syncthreads();
    }
}

// =====================================================================
// Per-head RMS norm + SiLU gate (writes tf32-rounded for the out GEMM)
// =====================================================================
__global__ void __launch_bounds__(256) norm_gate_kernel(const float* __restrict__ gnw)
{
    const int blk = blockIdx.x;
    const int row = blk >> 2, h = blk & 3;
    const long idx = (long)row * VDIM + h * DV + threadIdx.x;
    float xv = g_o[idx];
    float ss = xv * xv;
    #pragma unroll
    for (int off = 16; off; off >>= 1)
        ss += __shfl_xor_sync(0xffffffffu, ss, off);
    __shared__ float red[8];
    __shared__ float stot;
    int wid = threadIdx.x >> 5, lane = threadIdx.x & 31;
    if (lane == 0) red[wid] = ss;
    __syncthreads();
    if (threadIdx.x == 0) {
        float s = 0.f;
        #pragma unroll
        for (int w = 0; w < 8; w++) s += red[w];
        stot = s;
    }
    __syncthreads();
    float mean = stot * (1.f / 256.f);
    float rr = rsqrtf(mean + EPSN);
    float gv = g_g[idx];
    float sig = 1.f / (1.f + expf(-gv));
    g_o[idx] = tf32_rna(xv * rr * gnw[threadIdx.x] * (gv * sig));
}

// =====================================================================
// launch
// =====================================================================
extern "C" void kernel_launch(void* const* d_in, const int* in_sizes, int n_in,
                              void* d_out, int out_size)
{
    const float* x    = (const float*)d_in[0];
    const float* Wq   = (const float*)d_in[1];
    const float* Wk   = (const float*)d_in[2];
    const float* Wv   = (const float*)d_in[3];
    const float* Wg   = (const float*)d_in[4];
    const float* Wgk1 = (const float*)d_in[5];
    const float* Wgk2 = (const float*)d_in[6];
    const float* bgk2 = (const float*)d_in[7];
    const float* gnw  = (const float*)d_in[8];
    const float* Wo   = (const float*)d_in[9];
    float* out = (float*)d_out;

    float *q, *k, *G, *v, *g, *o, *xr, *WT, *WoT;
    cudaGetSymbolAddress((void**)&q,   g_q);
    cudaGetSymbolAddress((void**)&k,   g_k);
    cudaGetSymbolAddress((void**)&G,   g_G);
    cudaGetSymbolAddress((void**)&v,   g_v);
    cudaGetSymbolAddress((void**)&g,   g_g);
    cudaGetSymbolAddress((void**)&o,   g_o);
    cudaGetSymbolAddress((void**)&xr,  g_xr);
    cudaGetSymbolAddress((void**)&WT,  g_WT);
    cudaGetSymbolAddress((void**)&WoT, g_WoT);

    cudaFuncSetAttribute(scan_kernel,    cudaFuncAttributeMaxDynamicSharedMemorySize, SCAN_SMEM_BYTES);
    cudaFuncSetAttribute(intra_kernel,   cudaFuncAttributeMaxDynamicSharedMemorySize, INTRA_SMEM_BYTES);
    cudaFuncSetAttribute(gemm_mma_kernel,cudaFuncAttributeMaxDynamicSharedMemorySize, GEMM_SMEM);

    // preprocessing: round x, transpose+round weights into combined WT
    round_x_kernel<<<BT * DD / 1024, 256>>>(x);
    transpose_rna_kernel<<<dim3(512 / 32, DD / 32), 256>>>(Wq, WT,               512);
    transpose_rna_kernel<<<dim3(512 / 32, DD / 32), 256>>>(Wk, WT + 512 * DD,    512);
    transpose_rna_kernel<<<dim3(1024 / 32, DD / 32), 256>>>(Wv, WT + 1024 * DD, 1024);
    transpose_rna_kernel<<<dim3(1024 / 32, DD / 32), 256>>>(Wg, WT + 2048 * DD, 1024);
    transpose_rna_kernel<<<dim3(1024 / 32, DD / 32), 256>>>(Wo, WoT,            1024);

    // fused q/k/v/g projection GEMM (tensor cores via mma.sync)
    gemm_mma_kernel<<<dim3(24, 32), 256, GEMM_SMEM>>>(xr, WT, q, k, v, g, 0);

    // gate path
    proj16_kernel<<<BT, 256>>>(x, Wgk1);
    gk_kernel<<<BT, 512>>>(Wgk2, bgk2);
    cumsum_kernel<<<BB * NC, 512>>>();

    // attention
    scan_kernel<<<BB * HH * 8, 256, SCAN_SMEM_BYTES>>>();
    intra_kernel<<<NC * BB * HH, 256, INTRA_SMEM_BYTES>>>();

    // norm/gate + output projection (tensor cores via mma.sync)
    norm_gate_kernel<<<BT * HH, 256>>>(gnw);
    gemm_mma_kernel<<<dim3(8, 32), 256, GEMM_SMEM>>>(o, WoT, out, nullptr, nullptr, nullptr, 1);
}